// round 15
// baseline (speedup 1.0000x reference)
#include <cuda_runtime.h>
#include <cstdint>

#define B_  4
#define LQ_ 2048
#define LK_ 2048
#define D_  1024

// ---------------- scratch (static device globals; no runtime alloc) ----------
__device__ float g_wt  [(size_t)2 * D_ * D_];        // slot0: Mt=Wk@Wq^T ; slot1: Wv^T
__device__ float g_bias[2 * D_];                     // slot0: zeros ; slot1: bv
__device__ float g_y   [(size_t)B_ * LQ_ * D_];      // Y = Xq @ M (tf32-rounded)
__device__ float g_kr  [(size_t)B_ * LK_ * D_];      // tf32-rounded k_in
__device__ float g_vt  [(size_t)B_ * D_ * LK_];      // V^T per batch (tf32-rounded)
__device__ float g_s   [(size_t)B_ * LQ_ * LK_];     // unnormalized exp scores
__device__ float g_w   [D_];                         // w = Wk @ bq
__device__ float g_beta[(size_t)B_ * LK_];           // beta_j / 32 per key position
__device__ float g_rsum[(size_t)B_ * LQ_];           // row sums of exp scores

// ---------------- PTX helpers ------------------------------------------------
__device__ __forceinline__ uint32_t smem_u32(const void* p) {
    uint32_t a;
    asm("{ .reg .u64 t; cvta.to.shared.u64 t, %1; cvt.u32.u64 %0, t; }" : "=r"(a) : "l"(p));
    return a;
}
__device__ __forceinline__ float rna_tf32(float x) {
    uint32_t r; asm("cvt.rna.tf32.f32 %0, %1;" : "=r"(r) : "f"(x));
    return __uint_as_float(r);
}
__device__ __forceinline__ uint32_t rna_tf32_u(uint32_t x) {
    uint32_t r; asm("cvt.rna.tf32.f32 %0, %1;" : "=r"(r) : "f"(__uint_as_float(x)));
    return r;
}
__device__ __forceinline__ void cp16(uint32_t s, const void* g) {
    asm volatile("cp.async.cg.shared.global [%0], [%1], 16;" :: "r"(s), "l"(g));
}
#define CP_COMMIT() asm volatile("cp.async.commit_group;" ::: "memory")
#define CP_WAIT(n)  asm volatile("cp.async.wait_group %0;" :: "n"(n) : "memory")

__device__ __forceinline__ void ldsm4(uint32_t* r, uint32_t addr) {
    asm volatile("ldmatrix.sync.aligned.m8n8.x4.shared.b16 {%0,%1,%2,%3}, [%4];"
        : "=r"(r[0]), "=r"(r[1]), "=r"(r[2]), "=r"(r[3]) : "r"(addr));
}

__device__ __forceinline__ void mma_tf32(float* c, const uint32_t* a, const uint32_t* b) {
    asm volatile(
        "mma.sync.aligned.m16n8k8.row.col.f32.tf32.tf32.f32 "
        "{%0,%1,%2,%3}, {%4,%5,%6,%7}, {%8,%9}, {%0,%1,%2,%3};"
        : "+f"(c[0]), "+f"(c[1]), "+f"(c[2]), "+f"(c[3])
        : "r"(a[0]), "r"(a[1]), "r"(a[2]), "r"(a[3]), "r"(b[0]), "r"(b[1]));
}

// ---------------- tf32 mma.sync NT GEMM --------------------------------------
// C[M,N] = alpha * A[M,K] @ Bt[N,K]^T (+ bias), batched via blockIdx.z.
// Block tile 128x128x32; 256 threads = 8 warps in 4(M) x 2(N); warp tile 32x64.
// RND_A/RND_B: rna-round A/B fragments in-register (raw fp32 operands).
// EXP: epilogue applies expf and atomically accumulates row sums into rsum.
// SCALE: epilogue multiplies rows by 1/rsum[row] (PV normalization).
// TRANSC: for z==zTrans, epilogue writes C transposed into Ct via smem staging
//         (coalesced [D, LK]-per-batch stores).
#define BM 128
#define BN 128
#define BK 32
#define RST 36
#define STAGE_FLOATS ((BM + BN) * RST)   // 9216 floats = 36864 B
#define STAGES 3
#define GEMM_SMEM (STAGES * STAGE_FLOATS * 4)
#define RSTT 132                          // transpose-staging row stride (floats)

template <bool MULTI_A, bool RND_A, bool RND_B, bool BIAS, bool ROUND, bool TRANSC, bool EXP, bool SCALE>
__global__ __launch_bounds__(256, 2)
void gemm_tf32(const float* __restrict__ A0, const float* __restrict__ A1,
               const float* __restrict__ Bt,
               const float* __restrict__ bias, float* __restrict__ C,
               float* __restrict__ Ct, int zTrans, float* __restrict__ rsum,
               int N, int K, float alpha,
               size_t sA, size_t sB, size_t sC, int sBias)
{
    extern __shared__ float smf[];
    const uint32_t sb32 = smem_u32(smf);

    const int tid  = threadIdx.x;
    const int wid  = tid >> 5;
    const int lane = tid & 31;
    const int grp  = lane >> 2;   // 0..7
    const int q    = lane & 3;    // 0..3
    const int wm   = wid & 3;     // 4 warps along M -> 32 rows each
    const int wn   = wid >> 2;    // 2 warps along N -> 64 cols each

    const int m0 = blockIdx.y * BM;
    const int n0 = blockIdx.x * BN;
    const int z  = blockIdx.z;

    const float* Ab = MULTI_A ? (z == 0 ? A0 : A1) : A0 + (size_t)z * sA;
    const float* Bb = Bt + (size_t)z * sB;
    const float* biasb = BIAS ? (bias + (size_t)z * sBias) : nullptr;
    float* Cb = C + (size_t)z * sC;

    const int KT = K / BK;

    // per-lane ldmatrix byte offsets
    const uint32_t aoff =
        ((wm * 32 + (lane & 7) + ((lane >> 3) & 1) * 8) * RST + ((lane >> 4) & 1) * 4) * 4;
    const uint32_t boff =
        ((wn * 64 + (lane & 7) + ((lane >> 4) & 1) * 8) * RST + ((lane >> 3) & 1) * 4) * 4;

    // async load of one stage: A 128x32 + B 128x32, K-major rows (8 x 16B segs)
    auto load_stage = [&](int s, int kt) {
        const uint32_t abase = sb32 + s * STAGE_FLOATS * 4;
        const uint32_t bbase = abase + BM * RST * 4;
        const int k0 = kt * BK;
#pragma unroll
        for (int j = 0; j < 4; j++) {
            const int idx = tid + j * 256;          // 0..1023
            const int row = idx >> 3, seg = idx & 7;
            cp16(abase + (row * RST + seg * 4) * 4,
                 Ab + (size_t)(m0 + row) * K + k0 + seg * 4);
        }
#pragma unroll
        for (int j = 0; j < 4; j++) {
            const int idx = tid + j * 256;
            const int row = idx >> 3, seg = idx & 7;
            cp16(bbase + (row * RST + seg * 4) * 4,
                 Bb + (size_t)(n0 + row) * K + k0 + seg * 4);
        }
        CP_COMMIT();
    };

    float acc[2][8][4];
#pragma unroll
    for (int i = 0; i < 2; i++)
#pragma unroll
        for (int j = 0; j < 8; j++)
#pragma unroll
            for (int r = 0; r < 4; r++) acc[i][j][r] = 0.f;

    load_stage(0, 0);
    load_stage(1, 1);

    for (int kt = 0; kt < KT; kt++) {
        const int s = kt % STAGES;
        if (kt < KT - 1) { CP_WAIT(1); } else { CP_WAIT(0); }
        __syncthreads();

        if (kt + 2 < KT) load_stage((kt + 2) % STAGES, kt + 2);

        const uint32_t sa = sb32 + s * STAGE_FLOATS * 4;
        const uint32_t sbB = sa + BM * RST * 4;

#pragma unroll
        for (int kk = 0; kk < 4; kk++) {
            uint32_t af[2][4], bf[4][4];
#pragma unroll
            for (int mt = 0; mt < 2; mt++)
                ldsm4(af[mt], sa + aoff + mt * (16 * RST * 4) + kk * 32);
            if (RND_A) {
#pragma unroll
                for (int mt = 0; mt < 2; mt++)
#pragma unroll
                    for (int r = 0; r < 4; r++) af[mt][r] = rna_tf32_u(af[mt][r]);
            }
#pragma unroll
            for (int ntp = 0; ntp < 4; ntp++)
                ldsm4(bf[ntp], sbB + boff + ntp * (16 * RST * 4) + kk * 32);
            if (RND_B) {
#pragma unroll
                for (int ntp = 0; ntp < 4; ntp++)
#pragma unroll
                    for (int r = 0; r < 4; r++) bf[ntp][r] = rna_tf32_u(bf[ntp][r]);
            }
#pragma unroll
            for (int mt = 0; mt < 2; mt++)
#pragma unroll
                for (int nt = 0; nt < 8; nt++)
                    mma_tf32(acc[mt][nt], af[mt], bf[nt >> 1] + (nt & 1) * 2);
        }
    }

    // Epilogue
    const bool doTrans = TRANSC && (z == zTrans);
    if (TRANSC) {
        if (doTrans) __syncthreads();   // pipeline smem now reusable for staging
    }
#pragma unroll
    for (int mt = 0; mt < 2; mt++) {
        const int r = m0 + wm * 32 + mt * 16 + grp;
        float rs0 = 0.f, rs1 = 0.f;     // EXP: row-sum partials
        float inv0 = 1.f, inv1 = 1.f;   // SCALE: row normalizers
        if (SCALE) {
            inv0 = 1.f / rsum[(size_t)z * LQ_ + r];
            inv1 = 1.f / rsum[(size_t)z * LQ_ + r + 8];
        }
#pragma unroll
        for (int nt = 0; nt < 8; nt++) {
            const int c = n0 + wn * 64 + nt * 8 + q * 2;
            float2 v0, v1;
            v0.x = acc[mt][nt][0] * alpha;
            v0.y = acc[mt][nt][1] * alpha;
            v1.x = acc[mt][nt][2] * alpha;
            v1.y = acc[mt][nt][3] * alpha;
            if (BIAS) {
                const float2 bb = *(const float2*)(biasb + c);
                v0.x += bb.x; v0.y += bb.y;
                v1.x += bb.x; v1.y += bb.y;
            }
            if (EXP) {
                v0.x = __expf(v0.x); v0.y = __expf(v0.y);
                v1.x = __expf(v1.x); v1.y = __expf(v1.y);
            }
            if (SCALE) {
                v0.x *= inv0; v0.y *= inv0;
                v1.x *= inv1; v1.y *= inv1;
            }
            if (ROUND) {
                v0.x = rna_tf32(v0.x); v0.y = rna_tf32(v0.y);
                v1.x = rna_tf32(v1.x); v1.y = rna_tf32(v1.y);
            }
            if (EXP) {
                rs0 += v0.x + v0.y;
                rs1 += v1.x + v1.y;
            }
            if (doTrans) {
                // stage transposed: ts[d][l] with d = c - n0, l = r - m0 (stride RSTT)
                const int lc = c - n0;
                const int lr = r - m0;
                smf[(lc)     * RSTT + lr]     = v0.x;
                smf[(lc + 1) * RSTT + lr]     = v0.y;
                smf[(lc)     * RSTT + lr + 8] = v1.x;
                smf[(lc + 1) * RSTT + lr + 8] = v1.y;
            } else {
                *(float2*)(Cb + (size_t)r * N + c)       = v0;
                *(float2*)(Cb + (size_t)(r + 8) * N + c) = v1;
            }
        }
        if (EXP) {
            rs0 += __shfl_xor_sync(0xFFFFFFFFu, rs0, 1);
            rs0 += __shfl_xor_sync(0xFFFFFFFFu, rs0, 2);
            rs1 += __shfl_xor_sync(0xFFFFFFFFu, rs1, 1);
            rs1 += __shfl_xor_sync(0xFFFFFFFFu, rs1, 2);
            if (q == 0) {
                atomicAdd(rsum + (size_t)z * LQ_ + r,     rs0);
                atomicAdd(rsum + (size_t)z * LQ_ + r + 8, rs1);
            }
        }
    }
    if (TRANSC) {
        if (doTrans) {
            __syncthreads();
            // coalesced writeout: warp w handles d-rows [w*16, w*16+16)
            const int b0 = m0 >> 11;          // batch
            const int l0 = m0 & 2047;         // seq offset within batch
            float* dst = Ct + (size_t)b0 * D_ * LK_ + l0 + lane * 4;
#pragma unroll
            for (int dd = 0; dd < 16; dd++) {
                const int d = wid * 16 + dd;
                const float4 v = *(const float4*)&smf[d * RSTT + lane * 4];
                *(float4*)(dst + (size_t)(n0 + d) * LK_) = v;
            }
        }
    }
}

// ---------------- fused prep kernel ------------------------------------------
// Block ranges (grid.x = 1568, 256 threads):
//   [0, 1024):    transpose+round Wv [D,D] -> g_wt slot1  (32x32 tiles)
//   [1024, 1056): bias init (slot0=0, slot1=bv) + rsum zero
//   [1056, 1568): matvec w = Wk @ bq  (2 rows per block, 128 threads each)
__global__ __launch_bounds__(256)
void prep_fused_k(const float* __restrict__ Wv, const float* __restrict__ bv,
                  const float* __restrict__ Wk, const float* __restrict__ bq,
                  float* __restrict__ wvt, float* __restrict__ bias_out,
                  float* __restrict__ rsum, float* __restrict__ w)
{
    __shared__ float t[32][33];
    const int bx = blockIdx.x;

    if (bx < 1024) {
        const int c0 = (bx & 31) * 32, r0 = (bx >> 5) * 32;
        const int tx = threadIdx.x & 31, ty = threadIdx.x >> 5;
#pragma unroll
        for (int i = 0; i < 32; i += 8)
            t[ty + i][tx] = Wv[(size_t)(r0 + ty + i) * D_ + c0 + tx];
        __syncthreads();
#pragma unroll
        for (int i = 0; i < 32; i += 8)
            wvt[(size_t)(c0 + ty + i) * D_ + r0 + tx] = rna_tf32(t[tx][ty + i]);
    } else if (bx < 1056) {
        const int i = (bx - 1024) * 256 + threadIdx.x;   // 0..8191
        if (i < D_)           bias_out[i] = 0.f;
        else if (i < 2 * D_)  bias_out[i] = bv[i - D_];
        rsum[i] = 0.f;
    } else {
        const int sub = threadIdx.x >> 7;                 // 2 rows per block
        const int tt  = threadIdx.x & 127;
        const int row = (bx - 1056) * 2 + sub;
        const float* p = Wk + (size_t)row * D_;
        float s = 0.f;
        for (int i = tt * 4; i < D_; i += 512) {
            const float4 a = *(const float4*)(p + i);
            const float4 b = *(const float4*)(bq + i);
            s += a.x * b.x + a.y * b.y + a.z * b.z + a.w * b.w;
        }
#pragma unroll
        for (int o = 16; o; o >>= 1) s += __shfl_xor_sync(0xFFFFFFFFu, s, o);
        if ((tt & 31) == 0) t[sub][tt >> 5] = s;
        __syncthreads();
        if (tt == 0) w[row] = t[sub][0] + t[sub][1] + t[sub][2] + t[sub][3];
    }
}

// beta[row] = (Xk[row,:] . w) / 32 ; also writes tf32-rounded Xk into kr.
__global__ __launch_bounds__(256)
void beta_k(const float* __restrict__ xk, const float* __restrict__ w,
            float* __restrict__ beta, float* __restrict__ kr)
{
    const int row  = blockIdx.x * 8 + (threadIdx.x >> 5);
    const int lane = threadIdx.x & 31;
    const float* p = xk + (size_t)row * D_;
    float*       o = kr + (size_t)row * D_;
    float s = 0.f;
    for (int i = lane * 4; i < D_; i += 128) {
        float4 a = *(const float4*)(p + i);
        const float4 b = *(const float4*)(w + i);
        s += a.x * b.x + a.y * b.y + a.z * b.z + a.w * b.w;
        a.x = rna_tf32(a.x); a.y = rna_tf32(a.y);
        a.z = rna_tf32(a.z); a.w = rna_tf32(a.w);
        *(float4*)(o + i) = a;
    }
#pragma unroll
    for (int of = 16; of; of >>= 1) s += __shfl_xor_sync(0xFFFFFFFFu, s, of);
    if (lane == 0) beta[row] = s * (1.f / 32.f);
}

// ---------------- host -------------------------------------------------------
extern "C" void kernel_launch(void* const* d_in, const int* in_sizes, int n_in,
                              void* d_out, int out_size)
{
    const float* q_in = (const float*)d_in[0];
    const float* k_in = (const float*)d_in[1];
    const float* v_in = (const float*)d_in[2];
    const float* Wq   = (const float*)d_in[3];
    const float* bq   = (const float*)d_in[4];
    const float* Wk   = (const float*)d_in[5];
    // bk (d_in[6]) cancels in row-softmax; unused.
    const float* Wv   = (const float*)d_in[7];
    const float* bv   = (const float*)d_in[8];
    float* out = (float*)d_out;

    float *pwt, *pbias, *py, *pkr, *pvt, *ps, *pw, *pbeta, *prs;
    cudaGetSymbolAddress((void**)&pwt,   g_wt);
    cudaGetSymbolAddress((void**)&pbias, g_bias);
    cudaGetSymbolAddress((void**)&py,    g_y);
    cudaGetSymbolAddress((void**)&pkr,   g_kr);
    cudaGetSymbolAddress((void**)&pvt,   g_vt);
    cudaGetSymbolAddress((void**)&ps,    g_s);
    cudaGetSymbolAddress((void**)&pw,    g_w);
    cudaGetSymbolAddress((void**)&pbeta, g_beta);
    cudaGetSymbolAddress((void**)&prs,   g_rsum);

    cudaFuncSetAttribute((const void*)gemm_tf32<false, true,  true,  false, true,  false, false, false>,
                         cudaFuncAttributeMaxDynamicSharedMemorySize, GEMM_SMEM);
    cudaFuncSetAttribute((const void*)gemm_tf32<true,  true,  false, true,  true,  true,  false, false>,
                         cudaFuncAttributeMaxDynamicSharedMemorySize, GEMM_SMEM);
    cudaFuncSetAttribute((const void*)gemm_tf32<false, false, false, true,  true,  false, true,  false>,
                         cudaFuncAttributeMaxDynamicSharedMemorySize, GEMM_SMEM);
    cudaFuncSetAttribute((const void*)gemm_tf32<false, false, false, false, false, false, false, true >,
                         cudaFuncAttributeMaxDynamicSharedMemorySize, GEMM_SMEM);

    const size_t T = (size_t)B_ * LQ_ * D_;

    // 1) fused prep: Wv^T rounded -> g_wt slot1 ; biases+rsum ; w = Wk@bq
    prep_fused_k<<<1568, 256>>>(Wv, bv, Wk, bq,
                                pwt + (size_t)D_ * D_, pbias, prs, pw);

    // 2) beta + rounded Kr (needs w)
    beta_k<<<(B_ * LK_) / 8, 256>>>(k_in, pw, pbeta, pkr);

    // 3) Mt = rna(Wk) @ rna(Wq)^T -> g_wt slot0  (raw operands, in-fragment rounding)
    gemm_tf32<false, true, true, false, true, false, false, false>
        <<<dim3(D_ / BN, D_ / BM, 1), 256, GEMM_SMEM>>>(
        Wk, nullptr, Wq, nullptr, pwt, nullptr, -1, nullptr, D_, D_, 1.f, 0, 0, 0, 0);

    // 4) projections: z=0: Y = rna(Xq) @ Mt^T -> g_y ; z=1: V = rna(Xv) @ Wv^T + bv -> g_vt (transposed, staged)
    gemm_tf32<true, true, false, true, true, true, false, false>
        <<<dim3(D_ / BN, (B_ * LQ_) / BM, 2), 256, GEMM_SMEM>>>(
        q_in, v_in, pwt, pbias, py, pvt, /*zTrans=*/1, nullptr, D_, D_, 1.f,
        0, (size_t)D_ * D_, T, D_);

    // 5) scores: P~ = rna(exp(Y @ Kr^T / 32 + beta)) ; row sums -> g_rsum (atomics)
    gemm_tf32<false, false, false, true, true, false, true, false>
        <<<dim3(LK_ / BN, LQ_ / BM, B_), 256, GEMM_SMEM>>>(
        py, nullptr, pkr, pbeta, ps, nullptr, -1, prs,
        LK_, D_, 1.f / 32.f,
        (size_t)LQ_ * D_, (size_t)LK_ * D_, (size_t)LQ_ * LK_, LK_);

    // 6) O = (P~ @ V) / rsum  (V^T is [D, LK] K-major; row-normalize in epilogue)
    gemm_tf32<false, false, false, false, false, false, false, true>
        <<<dim3(D_ / BN, LQ_ / BM, B_), 256, GEMM_SMEM>>>(
        ps, nullptr, pvt, nullptr, out, nullptr, -1, prs,
        D_, LK_, 1.f,
        (size_t)LQ_ * LK_, (size_t)D_ * LK_, (size_t)LQ_ * D_, 0);
}

// round 16
// speedup vs baseline: 1.0163x; 1.0163x over previous
#include <cuda_runtime.h>
#include <cstdint>

#define B_  4
#define LQ_ 2048
#define LK_ 2048
#define D_  1024

// ---------------- scratch (static device globals; no runtime alloc) ----------
__device__ float g_wt  [(size_t)2 * D_ * D_];        // slot0: Mt=Wk@Wq^T ; slot1: Wv^T
__device__ float g_bias[2 * D_];                     // slot0: zeros ; slot1: bv
__device__ float g_y   [(size_t)B_ * LQ_ * D_];      // Y = Xq @ M (tf32-rounded)
__device__ float g_kr  [(size_t)B_ * LK_ * D_];      // tf32-rounded k_in
__device__ float g_vt  [(size_t)B_ * D_ * LK_];      // V^T per batch (tf32-rounded)
__device__ float g_s   [(size_t)B_ * LQ_ * LK_];     // unnormalized exp scores
__device__ float g_w   [D_];                         // w = Wk @ bq
__device__ float g_beta[(size_t)B_ * LK_];           // beta_j / 32 per key position
__device__ float g_rsum[(size_t)B_ * LQ_];           // row sums of exp scores

// ---------------- PTX helpers ------------------------------------------------
__device__ __forceinline__ uint32_t smem_u32(const void* p) {
    uint32_t a;
    asm("{ .reg .u64 t; cvta.to.shared.u64 t, %1; cvt.u32.u64 %0, t; }" : "=r"(a) : "l"(p));
    return a;
}
__device__ __forceinline__ float rna_tf32(float x) {
    uint32_t r; asm("cvt.rna.tf32.f32 %0, %1;" : "=r"(r) : "f"(x));
    return __uint_as_float(r);
}
__device__ __forceinline__ uint32_t rna_tf32_u(uint32_t x) {
    uint32_t r; asm("cvt.rna.tf32.f32 %0, %1;" : "=r"(r) : "f"(__uint_as_float(x)));
    return r;
}
__device__ __forceinline__ void cp16(uint32_t s, const void* g) {
    asm volatile("cp.async.cg.shared.global [%0], [%1], 16;" :: "r"(s), "l"(g));
}
#define CP_COMMIT() asm volatile("cp.async.commit_group;" ::: "memory")
#define CP_WAIT(n)  asm volatile("cp.async.wait_group %0;" :: "n"(n) : "memory")

__device__ __forceinline__ void ldsm4(uint32_t* r, uint32_t addr) {
    asm volatile("ldmatrix.sync.aligned.m8n8.x4.shared.b16 {%0,%1,%2,%3}, [%4];"
        : "=r"(r[0]), "=r"(r[1]), "=r"(r[2]), "=r"(r[3]) : "r"(addr));
}

__device__ __forceinline__ void mma_tf32(float* c, const uint32_t* a, const uint32_t* b) {
    asm volatile(
        "mma.sync.aligned.m16n8k8.row.col.f32.tf32.tf32.f32 "
        "{%0,%1,%2,%3}, {%4,%5,%6,%7}, {%8,%9}, {%0,%1,%2,%3};"
        : "+f"(c[0]), "+f"(c[1]), "+f"(c[2]), "+f"(c[3])
        : "r"(a[0]), "r"(a[1]), "r"(a[2]), "r"(a[3]), "r"(b[0]), "r"(b[1]));
}

// ---------------- tf32 mma.sync NT GEMM (device body) -------------------------
// C[M,N] = alpha * A[M,K] @ Bt[N,K]^T (+ bias), batch via bz; tile (bx, by).
// Block tile 128x128x32; 256 threads = 8 warps in 4(M) x 2(N); warp tile 32x64.
// RND_A/RND_B: rna-round A/B fragments in-register (raw fp32 operands).
// EXP: epilogue applies expf and atomically accumulates row sums into rsum.
// SCALE: epilogue multiplies rows by 1/rsum[row] (PV normalization).
// TRANSC: for z==zTrans, epilogue writes C transposed into Ct ([D, LK] per batch).
#define BM 128
#define BN 128
#define BK 32
#define RST 36
#define STAGE_FLOATS ((BM + BN) * RST)   // 9216 floats = 36864 B
#define STAGES 3
#define GEMM_SMEM (STAGES * STAGE_FLOATS * 4)

template <bool MULTI_A, bool RND_A, bool RND_B, bool BIAS, bool ROUND, bool TRANSC, bool EXP, bool SCALE>
__device__ __forceinline__
void gemm_dev(const float* __restrict__ A0, const float* __restrict__ A1,
              const float* __restrict__ Bt,
              const float* __restrict__ bias, float* __restrict__ C,
              float* __restrict__ Ct, int zTrans, float* __restrict__ rsum,
              int N, int K, float alpha,
              size_t sA, size_t sB, size_t sC, int sBias,
              int bx, int by, int bz, float* smf)
{
    const uint32_t sb32 = smem_u32(smf);

    const int tid  = threadIdx.x;
    const int wid  = tid >> 5;
    const int lane = tid & 31;
    const int grp  = lane >> 2;   // 0..7
    const int q    = lane & 3;    // 0..3
    const int wm   = wid & 3;     // 4 warps along M -> 32 rows each
    const int wn   = wid >> 2;    // 2 warps along N -> 64 cols each

    const int m0 = by * BM;
    const int n0 = bx * BN;
    const int z  = bz;

    const float* Ab = MULTI_A ? (z == 0 ? A0 : A1) : A0 + (size_t)z * sA;
    const float* Bb = Bt + (size_t)z * sB;
    const float* biasb = BIAS ? (bias + (size_t)z * sBias) : nullptr;
    float* Cb = C + (size_t)z * sC;

    const int KT = K / BK;

    // per-lane ldmatrix byte offsets
    const uint32_t aoff =
        ((wm * 32 + (lane & 7) + ((lane >> 3) & 1) * 8) * RST + ((lane >> 4) & 1) * 4) * 4;
    const uint32_t boff =
        ((wn * 64 + (lane & 7) + ((lane >> 4) & 1) * 8) * RST + ((lane >> 3) & 1) * 4) * 4;

    // async load of one stage: A 128x32 + B 128x32, K-major rows (8 x 16B segs)
    auto load_stage = [&](int s, int kt) {
        const uint32_t abase = sb32 + s * STAGE_FLOATS * 4;
        const uint32_t bbase = abase + BM * RST * 4;
        const int k0 = kt * BK;
#pragma unroll
        for (int j = 0; j < 4; j++) {
            const int idx = tid + j * 256;          // 0..1023
            const int row = idx >> 3, seg = idx & 7;
            cp16(abase + (row * RST + seg * 4) * 4,
                 Ab + (size_t)(m0 + row) * K + k0 + seg * 4);
        }
#pragma unroll
        for (int j = 0; j < 4; j++) {
            const int idx = tid + j * 256;
            const int row = idx >> 3, seg = idx & 7;
            cp16(bbase + (row * RST + seg * 4) * 4,
                 Bb + (size_t)(n0 + row) * K + k0 + seg * 4);
        }
        CP_COMMIT();
    };

    float acc[2][8][4];
#pragma unroll
    for (int i = 0; i < 2; i++)
#pragma unroll
        for (int j = 0; j < 8; j++)
#pragma unroll
            for (int r = 0; r < 4; r++) acc[i][j][r] = 0.f;

    load_stage(0, 0);
    load_stage(1, 1);

    for (int kt = 0; kt < KT; kt++) {
        const int s = kt % STAGES;
        if (kt < KT - 1) { CP_WAIT(1); } else { CP_WAIT(0); }
        __syncthreads();

        if (kt + 2 < KT) load_stage((kt + 2) % STAGES, kt + 2);

        const uint32_t sa = sb32 + s * STAGE_FLOATS * 4;
        const uint32_t sbB = sa + BM * RST * 4;

#pragma unroll
        for (int kk = 0; kk < 4; kk++) {
            uint32_t af[2][4], bf[4][4];
#pragma unroll
            for (int mt = 0; mt < 2; mt++)
                ldsm4(af[mt], sa + aoff + mt * (16 * RST * 4) + kk * 32);
            if (RND_A) {
#pragma unroll
                for (int mt = 0; mt < 2; mt++)
#pragma unroll
                    for (int r = 0; r < 4; r++) af[mt][r] = rna_tf32_u(af[mt][r]);
            }
#pragma unroll
            for (int ntp = 0; ntp < 4; ntp++)
                ldsm4(bf[ntp], sbB + boff + ntp * (16 * RST * 4) + kk * 32);
            if (RND_B) {
#pragma unroll
                for (int ntp = 0; ntp < 4; ntp++)
#pragma unroll
                    for (int r = 0; r < 4; r++) bf[ntp][r] = rna_tf32_u(bf[ntp][r]);
            }
#pragma unroll
            for (int mt = 0; mt < 2; mt++)
#pragma unroll
                for (int nt = 0; nt < 8; nt++)
                    mma_tf32(acc[mt][nt], af[mt], bf[nt >> 1] + (nt & 1) * 2);
        }
    }

    // Epilogue
    const bool doTrans = TRANSC && (z == zTrans);
#pragma unroll
    for (int mt = 0; mt < 2; mt++) {
        const int r = m0 + wm * 32 + mt * 16 + grp;
        float rs0 = 0.f, rs1 = 0.f;     // EXP: row-sum partials
        float inv0 = 1.f, inv1 = 1.f;   // SCALE: row normalizers
        if (SCALE) {
            inv0 = 1.f / rsum[(size_t)z * LQ_ + r];
            inv1 = 1.f / rsum[(size_t)z * LQ_ + r + 8];
        }
#pragma unroll
        for (int nt = 0; nt < 8; nt++) {
            const int c = n0 + wn * 64 + nt * 8 + q * 2;
            float2 v0, v1;
            v0.x = acc[mt][nt][0] * alpha;
            v0.y = acc[mt][nt][1] * alpha;
            v1.x = acc[mt][nt][2] * alpha;
            v1.y = acc[mt][nt][3] * alpha;
            if (BIAS) {
                const float2 bb = *(const float2*)(biasb + c);
                v0.x += bb.x; v0.y += bb.y;
                v1.x += bb.x; v1.y += bb.y;
            }
            if (EXP) {
                v0.x = __expf(v0.x); v0.y = __expf(v0.y);
                v1.x = __expf(v1.x); v1.y = __expf(v1.y);
            }
            if (SCALE) {
                v0.x *= inv0; v0.y *= inv0;
                v1.x *= inv1; v1.y *= inv1;
            }
            if (ROUND) {
                v0.x = rna_tf32(v0.x); v0.y = rna_tf32(v0.y);
                v1.x = rna_tf32(v1.x); v1.y = rna_tf32(v1.y);
            }
            if (EXP) {
                rs0 += v0.x + v0.y;
                rs1 += v1.x + v1.y;
            }
            if (doTrans) {
                // rows r, r+8 are (batch b, seq l); write Ct[b][c][l] (Ct: [D, LK] per batch)
                const int b0 = r >> 11,       l0 = r & 2047;
                const int b1 = (r + 8) >> 11, l1 = (r + 8) & 2047;
                float* t0 = Ct + (size_t)b0 * D_ * LK_ + l0;
                float* t1 = Ct + (size_t)b1 * D_ * LK_ + l1;
                t0[(size_t)(c)     * LK_] = v0.x;
                t0[(size_t)(c + 1) * LK_] = v0.y;
                t1[(size_t)(c)     * LK_] = v1.x;
                t1[(size_t)(c + 1) * LK_] = v1.y;
            } else {
                *(float2*)(Cb + (size_t)r * N + c)       = v0;
                *(float2*)(Cb + (size_t)(r + 8) * N + c) = v1;
            }
        }
        if (EXP) {
            rs0 += __shfl_xor_sync(0xFFFFFFFFu, rs0, 1);
            rs0 += __shfl_xor_sync(0xFFFFFFFFu, rs0, 2);
            rs1 += __shfl_xor_sync(0xFFFFFFFFu, rs1, 1);
            rs1 += __shfl_xor_sync(0xFFFFFFFFu, rs1, 2);
            if (q == 0) {
                atomicAdd(rsum + (size_t)z * LQ_ + r,     rs0);
                atomicAdd(rsum + (size_t)z * LQ_ + r + 8, rs1);
            }
        }
    }
}

// __global__ wrapper for the standalone GEMM launches
template <bool MULTI_A, bool RND_A, bool RND_B, bool BIAS, bool ROUND, bool TRANSC, bool EXP, bool SCALE>
__global__ __launch_bounds__(256, 2)
void gemm_tf32(const float* __restrict__ A0, const float* __restrict__ A1,
               const float* __restrict__ Bt,
               const float* __restrict__ bias, float* __restrict__ C,
               float* __restrict__ Ct, int zTrans, float* __restrict__ rsum,
               int N, int K, float alpha,
               size_t sA, size_t sB, size_t sC, int sBias)
{
    extern __shared__ float smf[];
    gemm_dev<MULTI_A, RND_A, RND_B, BIAS, ROUND, TRANSC, EXP, SCALE>(
        A0, A1, Bt, bias, C, Ct, zTrans, rsum, N, K, alpha,
        sA, sB, sC, sBias, blockIdx.x, blockIdx.y, blockIdx.z, smf);
}

// ---------------- merged Mt GEMM + prep kernel --------------------------------
// grid.x = 64 + 1568 = 1632 blocks, 256 threads, GEMM_SMEM dynamic smem.
//   [0, 64):      Mt = rna(Wk) @ rna(Wq)^T tile (x = bx & 7, y = bx >> 3)
//   [64, 1088):   transpose+round Wv -> g_wt slot1 (32x32 tiles)
//   [1088, 1120): bias init (slot0=0, slot1=bv) + rsum zero
//   [1120, 1632): matvec w = Wk @ bq (2 rows per block)
__global__ __launch_bounds__(256, 2)
void mt_prep_k(const float* __restrict__ Wq, const float* __restrict__ Wk,
               const float* __restrict__ Wv, const float* __restrict__ bv,
               const float* __restrict__ bq,
               float* __restrict__ mt_out, float* __restrict__ wvt,
               float* __restrict__ bias_out, float* __restrict__ rsum,
               float* __restrict__ w)
{
    extern __shared__ float smf[];
    const int bx = blockIdx.x;

    if (bx < 64) {
        gemm_dev<false, true, true, false, true, false, false, false>(
            Wk, nullptr, Wq, nullptr, mt_out, nullptr, -1, nullptr,
            D_, D_, 1.f, 0, 0, 0, 0, bx & 7, bx >> 3, 0, smf);
        return;
    }
    const int px = bx - 64;
    if (px < 1024) {
        // transpose+round Wv tile
        float* t = smf;  // [32][33]
        const int c0 = (px & 31) * 32, r0 = (px >> 5) * 32;
        const int tx = threadIdx.x & 31, ty = threadIdx.x >> 5;
#pragma unroll
        for (int i = 0; i < 32; i += 8)
            t[(ty + i) * 33 + tx] = Wv[(size_t)(r0 + ty + i) * D_ + c0 + tx];
        __syncthreads();
#pragma unroll
        for (int i = 0; i < 32; i += 8)
            wvt[(size_t)(c0 + ty + i) * D_ + r0 + tx] = rna_tf32(t[tx * 33 + ty + i]);
    } else if (px < 1056) {
        const int i = (px - 1024) * 256 + threadIdx.x;   // 0..8191
        if (i < D_)           bias_out[i] = 0.f;
        else if (i < 2 * D_)  bias_out[i] = bv[i - D_];
        rsum[i] = 0.f;
    } else {
        float* t = smf;  // [2][4] partials
        const int sub = threadIdx.x >> 7;                 // 2 rows per block
        const int tt  = threadIdx.x & 127;
        const int row = (px - 1056) * 2 + sub;
        const float* p = Wk + (size_t)row * D_;
        float s = 0.f;
        for (int i = tt * 4; i < D_; i += 512) {
            const float4 a = *(const float4*)(p + i);
            const float4 b = *(const float4*)(bq + i);
            s += a.x * b.x + a.y * b.y + a.z * b.z + a.w * b.w;
        }
#pragma unroll
        for (int o = 16; o; o >>= 1) s += __shfl_xor_sync(0xFFFFFFFFu, s, o);
        if ((tt & 31) == 0) t[sub * 4 + (tt >> 5)] = s;
        __syncthreads();
        if (tt == 0) w[row] = t[sub * 4 + 0] + t[sub * 4 + 1] + t[sub * 4 + 2] + t[sub * 4 + 3];
    }
}

// beta[row] = (Xk[row,:] . w) / 32 ; also writes tf32-rounded Xk into kr.
__global__ __launch_bounds__(256)
void beta_k(const float* __restrict__ xk, const float* __restrict__ w,
            float* __restrict__ beta, float* __restrict__ kr)
{
    const int row  = blockIdx.x * 8 + (threadIdx.x >> 5);
    const int lane = threadIdx.x & 31;
    const float* p = xk + (size_t)row * D_;
    float*       o = kr + (size_t)row * D_;
    float s = 0.f;
    for (int i = lane * 4; i < D_; i += 128) {
        float4 a = *(const float4*)(p + i);
        const float4 b = *(const float4*)(w + i);
        s += a.x * b.x + a.y * b.y + a.z * b.z + a.w * b.w;
        a.x = rna_tf32(a.x); a.y = rna_tf32(a.y);
        a.z = rna_tf32(a.z); a.w = rna_tf32(a.w);
        *(float4*)(o + i) = a;
    }
#pragma unroll
    for (int of = 16; of; of >>= 1) s += __shfl_xor_sync(0xFFFFFFFFu, s, of);
    if (lane == 0) beta[row] = s * (1.f / 32.f);
}

// ---------------- host -------------------------------------------------------
extern "C" void kernel_launch(void* const* d_in, const int* in_sizes, int n_in,
                              void* d_out, int out_size)
{
    const float* q_in = (const float*)d_in[0];
    const float* k_in = (const float*)d_in[1];
    const float* v_in = (const float*)d_in[2];
    const float* Wq   = (const float*)d_in[3];
    const float* bq   = (const float*)d_in[4];
    const float* Wk   = (const float*)d_in[5];
    // bk (d_in[6]) cancels in row-softmax; unused.
    const float* Wv   = (const float*)d_in[7];
    const float* bv   = (const float*)d_in[8];
    float* out = (float*)d_out;

    float *pwt, *pbias, *py, *pkr, *pvt, *ps, *pw, *pbeta, *prs;
    cudaGetSymbolAddress((void**)&pwt,   g_wt);
    cudaGetSymbolAddress((void**)&pbias, g_bias);
    cudaGetSymbolAddress((void**)&py,    g_y);
    cudaGetSymbolAddress((void**)&pkr,   g_kr);
    cudaGetSymbolAddress((void**)&pvt,   g_vt);
    cudaGetSymbolAddress((void**)&ps,    g_s);
    cudaGetSymbolAddress((void**)&pw,    g_w);
    cudaGetSymbolAddress((void**)&pbeta, g_beta);
    cudaGetSymbolAddress((void**)&prs,   g_rsum);

    cudaFuncSetAttribute((const void*)mt_prep_k,
                         cudaFuncAttributeMaxDynamicSharedMemorySize, GEMM_SMEM);
    cudaFuncSetAttribute((const void*)gemm_tf32<true,  true,  false, true,  true,  true,  false, false>,
                         cudaFuncAttributeMaxDynamicSharedMemorySize, GEMM_SMEM);
    cudaFuncSetAttribute((const void*)gemm_tf32<false, false, false, true,  true,  false, true,  false>,
                         cudaFuncAttributeMaxDynamicSharedMemorySize, GEMM_SMEM);
    cudaFuncSetAttribute((const void*)gemm_tf32<false, false, false, false, false, false, false, true >,
                         cudaFuncAttributeMaxDynamicSharedMemorySize, GEMM_SMEM);

    const size_t T = (size_t)B_ * LQ_ * D_;

    // 1) merged: Mt = rna(Wk)@rna(Wq)^T -> slot0 ; Wv^T rounded -> slot1 ;
    //    biases+rsum ; w = Wk@bq    (independent pieces run concurrently)
    mt_prep_k<<<1632, 256, GEMM_SMEM>>>(Wq, Wk, Wv, bv, bq,
                                        pwt, pwt + (size_t)D_ * D_, pbias, prs, pw);

    // 2) beta + rounded Kr (needs w)
    beta_k<<<(B_ * LK_) / 8, 256>>>(k_in, pw, pbeta, pkr);

    // 3) projections: z=0: Y = rna(Xq) @ Mt^T -> g_y ; z=1: V = rna(Xv) @ Wv^T + bv -> g_vt (transposed)
    gemm_tf32<true, true, false, true, true, true, false, false>
        <<<dim3(D_ / BN, (B_ * LQ_) / BM, 2), 256, GEMM_SMEM>>>(
        q_in, v_in, pwt, pbias, py, pvt, /*zTrans=*/1, nullptr, D_, D_, 1.f,
        0, (size_t)D_ * D_, T, D_);

    // 4) scores: P~ = rna(exp(Y @ Kr^T / 32 + beta)) ; row sums -> g_rsum (atomics)
    gemm_tf32<false, false, false, true, true, false, true, false>
        <<<dim3(LK_ / BN, LQ_ / BM, B_), 256, GEMM_SMEM>>>(
        py, nullptr, pkr, pbeta, ps, nullptr, -1, prs,
        LK_, D_, 1.f / 32.f,
        (size_t)LQ_ * D_, (size_t)LK_ * D_, (size_t)LQ_ * LK_, LK_);

    // 5) O = (P~ @ V) / rsum  (V^T is [D, LK] K-major; row-normalize in epilogue)
    gemm_tf32<false, false, false, false, false, false, false, true>
        <<<dim3(D_ / BN, LQ_ / BM, B_), 256, GEMM_SMEM>>>(
        ps, nullptr, pvt, nullptr, out, nullptr, -1, prs,
        D_, LK_, 1.f,
        (size_t)LQ_ * LK_, (size_t)D_ * LK_, (size_t)LQ_ * D_, 0);
}

// round 17
// speedup vs baseline: 1.0269x; 1.0104x over previous
#include <cuda_runtime.h>
#include <cstdint>

#define B_  4
#define LQ_ 2048
#define LK_ 2048
#define D_  1024

// ---------------- scratch (static device globals; no runtime alloc) ----------
__device__ float g_wt  [(size_t)2 * D_ * D_];        // slot0: Mt=Wk@Wq^T ; slot1: Wv^T
__device__ float g_bias[2 * D_];                     // slot0: zeros ; slot1: bv
__device__ float g_y   [(size_t)B_ * LQ_ * D_];      // Y = Xq @ M (tf32-rounded)
__device__ float g_kr  [(size_t)B_ * LK_ * D_];      // tf32-rounded k_in
__device__ float g_vt  [(size_t)B_ * D_ * LK_];      // V^T per batch (tf32-rounded)
__device__ float g_s   [(size_t)B_ * LQ_ * LK_];     // unnormalized exp scores
__device__ float g_w   [D_];                         // w = Wk @ bq
__device__ float g_beta[(size_t)B_ * LK_];           // beta_j / 32 per key position
__device__ float g_rsum[(size_t)B_ * LQ_];           // row sums of exp scores

// ---------------- PTX helpers ------------------------------------------------
__device__ __forceinline__ uint32_t smem_u32(const void* p) {
    uint32_t a;
    asm("{ .reg .u64 t; cvta.to.shared.u64 t, %1; cvt.u32.u64 %0, t; }" : "=r"(a) : "l"(p));
    return a;
}
__device__ __forceinline__ float rna_tf32(float x) {
    uint32_t r; asm("cvt.rna.tf32.f32 %0, %1;" : "=r"(r) : "f"(x));
    return __uint_as_float(r);
}
__device__ __forceinline__ uint32_t rna_tf32_u(uint32_t x) {
    uint32_t r; asm("cvt.rna.tf32.f32 %0, %1;" : "=r"(r) : "f"(__uint_as_float(x)));
    return r;
}
__device__ __forceinline__ void cp16(uint32_t s, const void* g) {
    asm volatile("cp.async.cg.shared.global [%0], [%1], 16;" :: "r"(s), "l"(g));
}
#define CP_COMMIT() asm volatile("cp.async.commit_group;" ::: "memory")
#define CP_WAIT(n)  asm volatile("cp.async.wait_group %0;" :: "n"(n) : "memory")

__device__ __forceinline__ void ldsm4(uint32_t* r, uint32_t addr) {
    asm volatile("ldmatrix.sync.aligned.m8n8.x4.shared.b16 {%0,%1,%2,%3}, [%4];"
        : "=r"(r[0]), "=r"(r[1]), "=r"(r[2]), "=r"(r[3]) : "r"(addr));
}

__device__ __forceinline__ void mma_tf32(float* c, const uint32_t* a, const uint32_t* b) {
    asm volatile(
        "mma.sync.aligned.m16n8k8.row.col.f32.tf32.tf32.f32 "
        "{%0,%1,%2,%3}, {%4,%5,%6,%7}, {%8,%9}, {%0,%1,%2,%3};"
        : "+f"(c[0]), "+f"(c[1]), "+f"(c[2]), "+f"(c[3])
        : "r"(a[0]), "r"(a[1]), "r"(a[2]), "r"(a[3]), "r"(b[0]), "r"(b[1]));
}

// ---------------- tf32 mma.sync NT GEMM (device body) -------------------------
// C[M,N] = alpha * A[M,K] @ Bt[N,K]^T (+ bias), batch via bz; tile (bx, by).
// Block tile 128x128x32; 256 threads = 8 warps in 4(M) x 2(N); warp tile 32x64.
// RND_A/RND_B: rna-round A/B fragments in-register (raw fp32 operands).
// EXP: epilogue applies expf and atomically accumulates row sums into rsum.
// SCALE: epilogue multiplies rows by 1/rsum[row] (PV normalization).
// TRANSC: for z==zTrans, epilogue writes C transposed into Ct ([D, LK] per batch).
#define BM 128
#define BN 128
#define BK 32
#define RST 36
#define STAGE_FLOATS ((BM + BN) * RST)   // 9216 floats = 36864 B
#define STAGES 3
#define GEMM_SMEM (STAGES * STAGE_FLOATS * 4)

template <bool MULTI_A, bool RND_A, bool RND_B, bool BIAS, bool ROUND, bool TRANSC, bool EXP, bool SCALE>
__device__ __forceinline__
void gemm_dev(const float* __restrict__ A0, const float* __restrict__ A1,
              const float* __restrict__ Bt,
              const float* __restrict__ bias, float* __restrict__ C,
              float* __restrict__ Ct, int zTrans, float* __restrict__ rsum,
              int N, int K, float alpha,
              size_t sA, size_t sB, size_t sC, int sBias,
              int bx, int by, int bz, float* smf)
{
    const uint32_t sb32 = smem_u32(smf);

    const int tid  = threadIdx.x;
    const int wid  = tid >> 5;
    const int lane = tid & 31;
    const int grp  = lane >> 2;   // 0..7
    const int q    = lane & 3;    // 0..3
    const int wm   = wid & 3;     // 4 warps along M -> 32 rows each
    const int wn   = wid >> 2;    // 2 warps along N -> 64 cols each

    const int m0 = by * BM;
    const int n0 = bx * BN;
    const int z  = bz;

    const float* Ab = MULTI_A ? (z == 0 ? A0 : A1) : A0 + (size_t)z * sA;
    const float* Bb = Bt + (size_t)z * sB;
    const float* biasb = BIAS ? (bias + (size_t)z * sBias) : nullptr;
    float* Cb = C + (size_t)z * sC;

    const int KT = K / BK;

    // per-lane ldmatrix byte offsets
    const uint32_t aoff =
        ((wm * 32 + (lane & 7) + ((lane >> 3) & 1) * 8) * RST + ((lane >> 4) & 1) * 4) * 4;
    const uint32_t boff =
        ((wn * 64 + (lane & 7) + ((lane >> 4) & 1) * 8) * RST + ((lane >> 3) & 1) * 4) * 4;

    // async load of one stage: A 128x32 + B 128x32, K-major rows (8 x 16B segs)
    auto load_stage = [&](int s, int kt) {
        const uint32_t abase = sb32 + s * STAGE_FLOATS * 4;
        const uint32_t bbase = abase + BM * RST * 4;
        const int k0 = kt * BK;
#pragma unroll
        for (int j = 0; j < 4; j++) {
            const int idx = tid + j * 256;          // 0..1023
            const int row = idx >> 3, seg = idx & 7;
            cp16(abase + (row * RST + seg * 4) * 4,
                 Ab + (size_t)(m0 + row) * K + k0 + seg * 4);
        }
#pragma unroll
        for (int j = 0; j < 4; j++) {
            const int idx = tid + j * 256;
            const int row = idx >> 3, seg = idx & 7;
            cp16(bbase + (row * RST + seg * 4) * 4,
                 Bb + (size_t)(n0 + row) * K + k0 + seg * 4);
        }
        CP_COMMIT();
    };

    float acc[2][8][4];
#pragma unroll
    for (int i = 0; i < 2; i++)
#pragma unroll
        for (int j = 0; j < 8; j++)
#pragma unroll
            for (int r = 0; r < 4; r++) acc[i][j][r] = 0.f;

    load_stage(0, 0);
    load_stage(1, 1);

    for (int kt = 0; kt < KT; kt++) {
        const int s = kt % STAGES;
        if (kt < KT - 1) { CP_WAIT(1); } else { CP_WAIT(0); }
        __syncthreads();

        if (kt + 2 < KT) load_stage((kt + 2) % STAGES, kt + 2);

        const uint32_t sa = sb32 + s * STAGE_FLOATS * 4;
        const uint32_t sbB = sa + BM * RST * 4;

#pragma unroll
        for (int kk = 0; kk < 4; kk++) {
            uint32_t af[2][4], bf[4][4];
#pragma unroll
            for (int mt = 0; mt < 2; mt++)
                ldsm4(af[mt], sa + aoff + mt * (16 * RST * 4) + kk * 32);
            if (RND_A) {
#pragma unroll
                for (int mt = 0; mt < 2; mt++)
#pragma unroll
                    for (int r = 0; r < 4; r++) af[mt][r] = rna_tf32_u(af[mt][r]);
            }
#pragma unroll
            for (int ntp = 0; ntp < 4; ntp++)
                ldsm4(bf[ntp], sbB + boff + ntp * (16 * RST * 4) + kk * 32);
            if (RND_B) {
#pragma unroll
                for (int ntp = 0; ntp < 4; ntp++)
#pragma unroll
                    for (int r = 0; r < 4; r++) bf[ntp][r] = rna_tf32_u(bf[ntp][r]);
            }
#pragma unroll
            for (int mt = 0; mt < 2; mt++)
#pragma unroll
                for (int nt = 0; nt < 8; nt++)
                    mma_tf32(acc[mt][nt], af[mt], bf[nt >> 1] + (nt & 1) * 2);
        }
    }

    // Epilogue
    const bool doTrans = TRANSC && (z == zTrans);
#pragma unroll
    for (int mt = 0; mt < 2; mt++) {
        const int r = m0 + wm * 32 + mt * 16 + grp;
        float rs0 = 0.f, rs1 = 0.f;     // EXP: row-sum partials
        float inv0 = 1.f, inv1 = 1.f;   // SCALE: row normalizers
        if (SCALE) {
            inv0 = 1.f / rsum[(size_t)z * LQ_ + r];
            inv1 = 1.f / rsum[(size_t)z * LQ_ + r + 8];
        }
#pragma unroll
        for (int nt = 0; nt < 8; nt++) {
            const int c = n0 + wn * 64 + nt * 8 + q * 2;
            float2 v0, v1;
            v0.x = acc[mt][nt][0] * alpha;
            v0.y = acc[mt][nt][1] * alpha;
            v1.x = acc[mt][nt][2] * alpha;
            v1.y = acc[mt][nt][3] * alpha;
            if (BIAS) {
                const float2 bb = *(const float2*)(biasb + c);
                v0.x += bb.x; v0.y += bb.y;
                v1.x += bb.x; v1.y += bb.y;
            }
            if (EXP) {
                v0.x = __expf(v0.x); v0.y = __expf(v0.y);
                v1.x = __expf(v1.x); v1.y = __expf(v1.y);
            }
            if (SCALE) {
                v0.x *= inv0; v0.y *= inv0;
                v1.x *= inv1; v1.y *= inv1;
            }
            if (ROUND) {
                v0.x = rna_tf32(v0.x); v0.y = rna_tf32(v0.y);
                v1.x = rna_tf32(v1.x); v1.y = rna_tf32(v1.y);
            }
            if (EXP) {
                rs0 += v0.x + v0.y;
                rs1 += v1.x + v1.y;
            }
            if (doTrans) {
                // rows r, r+8 are (batch b, seq l); write Ct[b][c][l] (Ct: [D, LK] per batch)
                const int b0 = r >> 11,       l0 = r & 2047;
                const int b1 = (r + 8) >> 11, l1 = (r + 8) & 2047;
                float* t0 = Ct + (size_t)b0 * D_ * LK_ + l0;
                float* t1 = Ct + (size_t)b1 * D_ * LK_ + l1;
                t0[(size_t)(c)     * LK_] = v0.x;
                t0[(size_t)(c + 1) * LK_] = v0.y;
                t1[(size_t)(c)     * LK_] = v1.x;
                t1[(size_t)(c + 1) * LK_] = v1.y;
            } else {
                *(float2*)(Cb + (size_t)r * N + c)       = v0;
                *(float2*)(Cb + (size_t)(r + 8) * N + c) = v1;
            }
        }
        if (EXP) {
            rs0 += __shfl_xor_sync(0xFFFFFFFFu, rs0, 1);
            rs0 += __shfl_xor_sync(0xFFFFFFFFu, rs0, 2);
            rs1 += __shfl_xor_sync(0xFFFFFFFFu, rs1, 1);
            rs1 += __shfl_xor_sync(0xFFFFFFFFu, rs1, 2);
            if (q == 0) {
                atomicAdd(rsum + (size_t)z * LQ_ + r,     rs0);
                atomicAdd(rsum + (size_t)z * LQ_ + r + 8, rs1);
            }
        }
    }
}

// __global__ wrapper for the standalone GEMM launches
template <bool MULTI_A, bool RND_A, bool RND_B, bool BIAS, bool ROUND, bool TRANSC, bool EXP, bool SCALE>
__global__ __launch_bounds__(256, 2)
void gemm_tf32(const float* __restrict__ A0, const float* __restrict__ A1,
               const float* __restrict__ Bt,
               const float* __restrict__ bias, float* __restrict__ C,
               float* __restrict__ Ct, int zTrans, float* __restrict__ rsum,
               int N, int K, float alpha,
               size_t sA, size_t sB, size_t sC, int sBias)
{
    extern __shared__ float smf[];
    gemm_dev<MULTI_A, RND_A, RND_B, BIAS, ROUND, TRANSC, EXP, SCALE>(
        A0, A1, Bt, bias, C, Ct, zTrans, rsum, N, K, alpha,
        sA, sB, sC, sBias, blockIdx.x, blockIdx.y, blockIdx.z, smf);
}

// ---------------- merged Mt GEMM + prep kernel --------------------------------
// grid.x = 64 + 1568 = 1632 blocks, 256 threads, GEMM_SMEM dynamic smem.
//   [0, 64):      Mt = rna(Wk) @ rna(Wq)^T tile (x = bx & 7, y = bx >> 3)
//   [64, 1088):   transpose+round Wv -> g_wt slot1 (32x32 tiles)
//   [1088, 1120): bias init (slot0=0, slot1=bv) + rsum zero
//   [1120, 1632): matvec w = Wk @ bq (2 rows per block)
__global__ __launch_bounds__(256, 2)
void mt_prep_k(const float* __restrict__ Wq, const float* __restrict__ Wk,
               const float* __restrict__ Wv, const float* __restrict__ bv,
               const float* __restrict__ bq,
               float* __restrict__ mt_out, float* __restrict__ wvt,
               float* __restrict__ bias_out, float* __restrict__ rsum,
               float* __restrict__ w)
{
    extern __shared__ float smf[];
    const int bx = blockIdx.x;

    if (bx < 64) {
        gemm_dev<false, true, true, false, true, false, false, false>(
            Wk, nullptr, Wq, nullptr, mt_out, nullptr, -1, nullptr,
            D_, D_, 1.f, 0, 0, 0, 0, bx & 7, bx >> 3, 0, smf);
        return;
    }
    const int px = bx - 64;
    if (px < 1024) {
        // transpose+round Wv tile
        float* t = smf;  // [32][33]
        const int c0 = (px & 31) * 32, r0 = (px >> 5) * 32;
        const int tx = threadIdx.x & 31, ty = threadIdx.x >> 5;
#pragma unroll
        for (int i = 0; i < 32; i += 8)
            t[(ty + i) * 33 + tx] = Wv[(size_t)(r0 + ty + i) * D_ + c0 + tx];
        __syncthreads();
#pragma unroll
        for (int i = 0; i < 32; i += 8)
            wvt[(size_t)(c0 + ty + i) * D_ + r0 + tx] = rna_tf32(t[tx * 33 + ty + i]);
    } else if (px < 1056) {
        const int i = (px - 1024) * 256 + threadIdx.x;   // 0..8191
        if (i < D_)           bias_out[i] = 0.f;
        else if (i < 2 * D_)  bias_out[i] = bv[i - D_];
        rsum[i] = 0.f;
    } else {
        float* t = smf;  // [2][4] partials
        const int sub = threadIdx.x >> 7;                 // 2 rows per block
        const int tt  = threadIdx.x & 127;
        const int row = (px - 1056) * 2 + sub;
        const float* p = Wk + (size_t)row * D_;
        float s = 0.f;
        for (int i = tt * 4; i < D_; i += 512) {
            const float4 a = *(const float4*)(p + i);
            const float4 b = *(const float4*)(bq + i);
            s += a.x * b.x + a.y * b.y + a.z * b.z + a.w * b.w;
        }
#pragma unroll
        for (int o = 16; o; o >>= 1) s += __shfl_xor_sync(0xFFFFFFFFu, s, o);
        if ((tt & 31) == 0) t[sub * 4 + (tt >> 5)] = s;
        __syncthreads();
        if (tt == 0) w[row] = t[sub * 4 + 0] + t[sub * 4 + 1] + t[sub * 4 + 2] + t[sub * 4 + 3];
    }
}

// ---------------- merged projections + beta kernel ----------------------------
// grid.x = 1024 + 1024 = 2048 blocks, 256 threads, GEMM_SMEM dynamic smem.
//   [0, 1024):    projection GEMM tiles: x = bx & 7, y = (bx >> 3) & 63, z = bx >> 9
//                 z=0: Y = rna(Xq) @ Mt^T ; z=1: V = rna(Xv) @ Wv^T + bv -> g_vt (transposed)
//   [1024, 2048): beta blocks: 8 rows each (row = (bx-1024)*8 + warp); also writes Kr.
__global__ __launch_bounds__(256, 2)
void proj_beta_k(const float* __restrict__ q_in, const float* __restrict__ v_in,
                 const float* __restrict__ wt, const float* __restrict__ bias,
                 float* __restrict__ y, float* __restrict__ vt,
                 const float* __restrict__ xk, const float* __restrict__ w,
                 float* __restrict__ beta, float* __restrict__ kr)
{
    extern __shared__ float smf[];
    const int bx = blockIdx.x;

    if (bx < 1024) {
        const int x = bx & 7, yy = (bx >> 3) & 63, z = bx >> 9;
        gemm_dev<true, true, false, true, true, true, false, false>(
            q_in, v_in, wt, bias, y, vt, /*zTrans=*/1, nullptr,
            D_, D_, 1.f, 0, (size_t)D_ * D_, (size_t)B_ * LQ_ * D_, D_,
            x, yy, z, smf);
        return;
    }
    // beta part: beta[row] = (Xk[row,:] . w) / 32 ; Kr = rna(Xk)
    const int row  = (bx - 1024) * 8 + (threadIdx.x >> 5);
    const int lane = threadIdx.x & 31;
    const float* p = xk + (size_t)row * D_;
    float*       o = kr + (size_t)row * D_;
    float s = 0.f;
    for (int i = lane * 4; i < D_; i += 128) {
        float4 a = *(const float4*)(p + i);
        const float4 b = *(const float4*)(w + i);
        s += a.x * b.x + a.y * b.y + a.z * b.z + a.w * b.w;
        a.x = rna_tf32(a.x); a.y = rna_tf32(a.y);
        a.z = rna_tf32(a.z); a.w = rna_tf32(a.w);
        *(float4*)(o + i) = a;
    }
#pragma unroll
    for (int of = 16; of; of >>= 1) s += __shfl_xor_sync(0xFFFFFFFFu, s, of);
    if (lane == 0) beta[row] = s * (1.f / 32.f);
}

// ---------------- host -------------------------------------------------------
extern "C" void kernel_launch(void* const* d_in, const int* in_sizes, int n_in,
                              void* d_out, int out_size)
{
    const float* q_in = (const float*)d_in[0];
    const float* k_in = (const float*)d_in[1];
    const float* v_in = (const float*)d_in[2];
    const float* Wq   = (const float*)d_in[3];
    const float* bq   = (const float*)d_in[4];
    const float* Wk   = (const float*)d_in[5];
    // bk (d_in[6]) cancels in row-softmax; unused.
    const float* Wv   = (const float*)d_in[7];
    const float* bv   = (const float*)d_in[8];
    float* out = (float*)d_out;

    float *pwt, *pbias, *py, *pkr, *pvt, *ps, *pw, *pbeta, *prs;
    cudaGetSymbolAddress((void**)&pwt,   g_wt);
    cudaGetSymbolAddress((void**)&pbias, g_bias);
    cudaGetSymbolAddress((void**)&py,    g_y);
    cudaGetSymbolAddress((void**)&pkr,   g_kr);
    cudaGetSymbolAddress((void**)&pvt,   g_vt);
    cudaGetSymbolAddress((void**)&ps,    g_s);
    cudaGetSymbolAddress((void**)&pw,    g_w);
    cudaGetSymbolAddress((void**)&pbeta, g_beta);
    cudaGetSymbolAddress((void**)&prs,   g_rsum);

    cudaFuncSetAttribute((const void*)mt_prep_k,
                         cudaFuncAttributeMaxDynamicSharedMemorySize, GEMM_SMEM);
    cudaFuncSetAttribute((const void*)proj_beta_k,
                         cudaFuncAttributeMaxDynamicSharedMemorySize, GEMM_SMEM);
    cudaFuncSetAttribute((const void*)gemm_tf32<false, false, false, true,  true,  false, true,  false>,
                         cudaFuncAttributeMaxDynamicSharedMemorySize, GEMM_SMEM);
    cudaFuncSetAttribute((const void*)gemm_tf32<false, false, false, false, false, false, false, true >,
                         cudaFuncAttributeMaxDynamicSharedMemorySize, GEMM_SMEM);

    // 1) merged: Mt = rna(Wk)@rna(Wq)^T -> slot0 ; Wv^T rounded -> slot1 ;
    //    biases+rsum ; w = Wk@bq
    mt_prep_k<<<1632, 256, GEMM_SMEM>>>(Wq, Wk, Wv, bv, bq,
                                        pwt, pwt + (size_t)D_ * D_, pbias, prs, pw);

    // 2) merged: projections (Y, V^T) + beta/Kr (both depend only on step 1)
    proj_beta_k<<<2048, 256, GEMM_SMEM>>>(q_in, v_in, pwt, pbias, py, pvt,
                                          k_in, pw, pbeta, pkr);

    // 3) scores: P~ = rna(exp(Y @ Kr^T / 32 + beta)) ; row sums -> g_rsum (atomics)
    gemm_tf32<false, false, false, true, true, false, true, false>
        <<<dim3(LK_ / BN, LQ_ / BM, B_), 256, GEMM_SMEM>>>(
        py, nullptr, pkr, pbeta, ps, nullptr, -1, prs,
        LK_, D_, 1.f / 32.f,
        (size_t)LQ_ * D_, (size_t)LK_ * D_, (size_t)LQ_ * LK_, LK_);

    // 4) O = (P~ @ V) / rsum  (V^T is [D, LK] K-major; row-normalize in epilogue)
    gemm_tf32<false, false, false, false, false, false, false, true>
        <<<dim3(D_ / BN, LQ_ / BM, B_), 256, GEMM_SMEM>>>(
        ps, nullptr, pvt, nullptr, out, nullptr, -1, prs,
        D_, LK_, 1.f,
        (size_t)LQ_ * LK_, (size_t)D_ * LK_, (size_t)LQ_ * D_, 0);
}